// round 1
// baseline (speedup 1.0000x reference)
#include <cuda_runtime.h>
#include <cuda_bf16.h>
#include <cstdint>

// ESN reservoir: B=256, T=4096, D=8, U=64, leaky=1.0
// state_t = tanh(inputs[b,t,:] @ W_in + b + state_{t-1} @ W_rec)
// W_rec is ~1/64 dense (about 64 nonzeros total) -> CSC sparse gather.

#define BATCH 256
#define TLEN  4096
#define DIN   8
#define UNITS 64
#define NZCAP 10
#define CHUNK 64          // timesteps of input staged per cp.async group
#define NCHUNK (TLEN / CHUNK)

// Sparse CSC of W_rec: for column u, rows g_src[u][k] with values g_val[u][k],
// zero-padded to NZCAP.
__device__ int   g_src[UNITS][NZCAP];
__device__ float g_val[UNITS][NZCAP];

__global__ void esn_prep_kernel(const float* __restrict__ W_rec) {
    int u = threadIdx.x;
    if (u >= UNITS) return;
    int cnt = 0;
    for (int j = 0; j < UNITS; ++j) {
        float v = W_rec[j * UNITS + u];
        if (v != 0.0f && cnt < NZCAP) {
            g_src[u][cnt] = j;
            g_val[u][cnt] = v;
            ++cnt;
        }
    }
    for (int k = cnt; k < NZCAP; ++k) {
        g_src[u][k] = 0;
        g_val[u][k] = 0.0f;
    }
}

// Accurate-enough tanh: Taylor (odd, through x^7) for |x|<0.4,
// 1 - 2/(exp2(2x/ln2)+1) via MUFU for larger |x|. Max rel err ~2e-5.
__device__ __forceinline__ float fast_tanh(float x) {
    float ax = fabsf(x);
    // large-branch value
    float e;
    asm("ex2.approx.f32 %0, %1;" : "=f"(e) : "f"(ax * 2.8853900817779268f)); // 2/ln2
    float r;
    asm("rcp.approx.f32 %0, %1;" : "=f"(r) : "f"(e + 1.0f));
    float large = __int_as_float(__float_as_int(1.0f - 2.0f * r) |
                                 (__float_as_int(x) & 0x80000000));
    // small-branch polynomial (odd in x, so sign comes for free)
    float x2 = x * x;
    float p = -0.05396825397f;            // -17/315
    p = fmaf(p, x2,  0.13333333333f);     //  2/15
    p = fmaf(p, x2, -0.33333333333f);     // -1/3
    p = fmaf(p, x2,  1.0f);
    float small = x * p;
    return (ax < 0.4f) ? small : large;
}

__device__ __forceinline__ void cp_async16(void* smem_dst, const void* gmem_src) {
    uint32_t s = (uint32_t)__cvta_generic_to_shared(smem_dst);
    asm volatile("cp.async.cg.shared.global [%0], [%1], 16;\n" :: "r"(s), "l"(gmem_src));
}
__device__ __forceinline__ void cp_async_commit() {
    asm volatile("cp.async.commit_group;\n");
}
__device__ __forceinline__ void cp_async_wait1() {
    asm volatile("cp.async.wait_group 1;\n");
}

__global__ void __launch_bounds__(32, 8)
esn_main_kernel(const float* __restrict__ inputs,
                const float* __restrict__ W_in,
                const float* __restrict__ bias,
                float* __restrict__ out) {
    const int b    = blockIdx.x;
    const int lane = threadIdx.x;          // 0..31; owns units lane and lane+32

    __shared__ float st[2][UNITS];         // double-buffered state
    __shared__ float xin[2][CHUNK * DIN];  // double-buffered staged inputs

    // Per-thread constants (registers)
    float win0[DIN], win1[DIN];
#pragma unroll
    for (int d = 0; d < DIN; ++d) {
        win0[d] = W_in[d * UNITS + lane];
        win1[d] = W_in[d * UNITS + lane + 32];
    }
    const float b0 = bias[lane];
    const float b1 = bias[lane + 32];

    int   s0[NZCAP], s1[NZCAP];
    float v0[NZCAP], v1[NZCAP];
#pragma unroll
    for (int k = 0; k < NZCAP; ++k) {
        s0[k] = g_src[lane][k];       v0[k] = g_val[lane][k];
        s1[k] = g_src[lane + 32][k];  v1[k] = g_val[lane + 32][k];
    }

    // init state (read buffer for t=0 is st[0])
    st[0][lane]      = 0.0f;
    st[0][lane + 32] = 0.0f;

    const float* inp_b = inputs + (size_t)b * TLEN * DIN;
    float*       out_b = out    + (size_t)b * TLEN * UNITS;

    // Prefetch chunks 0 and 1. Each chunk = CHUNK*DIN*4 = 2048B; each lane
    // copies 4x16B at byte offset lane*64.
#pragma unroll
    for (int c = 0; c < 2; ++c) {
        const float* src = inp_b + c * CHUNK * DIN;
#pragma unroll
        for (int i = 0; i < 4; ++i) {
            int fo = lane * 16 + i * 4;  // float offset
            cp_async16(&xin[c][fo], src + fo);
        }
        cp_async_commit();
    }
    __syncwarp();

    for (int c = 0; c < NCHUNK; ++c) {
        cp_async_wait1();
        __syncwarp();
        const int buf = c & 1;

        for (int tt = 0; tt < CHUNK; ++tt) {
            const int t  = c * CHUNK + tt;
            const int rb = t & 1;           // read state buffer
            const int wb = rb ^ 1;          // write state buffer

            // input vector (broadcast LDS.128 x2)
            const float4 xa = *(const float4*)&xin[buf][tt * DIN];
            const float4 xb = *(const float4*)&xin[buf][tt * DIN + 4];

            // input projection (off the critical chain)
            float a0 = b0, a1 = b1;
            a0 = fmaf(win0[0], xa.x, a0); a1 = fmaf(win1[0], xa.x, a1);
            a0 = fmaf(win0[1], xa.y, a0); a1 = fmaf(win1[1], xa.y, a1);
            a0 = fmaf(win0[2], xa.z, a0); a1 = fmaf(win1[2], xa.z, a1);
            a0 = fmaf(win0[3], xa.w, a0); a1 = fmaf(win1[3], xa.w, a1);
            a0 = fmaf(win0[4], xb.x, a0); a1 = fmaf(win1[4], xb.x, a1);
            a0 = fmaf(win0[5], xb.y, a0); a1 = fmaf(win1[5], xb.y, a1);
            a0 = fmaf(win0[6], xb.z, a0); a1 = fmaf(win1[6], xb.z, a1);
            a0 = fmaf(win0[7], xb.w, a0); a1 = fmaf(win1[7], xb.w, a1);

            // sparse recurrent gather (the critical chain)
            const float* s = st[rb];
#pragma unroll
            for (int k = 0; k < NZCAP; ++k) {
                a0 = fmaf(v0[k], s[s0[k]], a0);
                a1 = fmaf(v1[k], s[s1[k]], a1);
            }

            const float n0 = fast_tanh(a0);
            const float n1 = fast_tanh(a1);

            // write output (fire-and-forget, coalesced)
            out_b[(size_t)t * UNITS + lane]      = n0;
            out_b[(size_t)t * UNITS + lane + 32] = n1;

            // publish new state
            st[wb][lane]      = n0;
            st[wb][lane + 32] = n1;
            __syncwarp();
        }

        // prefetch chunk c+2 into the buffer just consumed
        if (c + 2 < NCHUNK) {
            const float* src = inp_b + (c + 2) * CHUNK * DIN;
#pragma unroll
            for (int i = 0; i < 4; ++i) {
                int fo = lane * 16 + i * 4;
                cp_async16(&xin[buf][fo], src + fo);
            }
        }
        cp_async_commit();   // commit even if empty to keep wait_group bookkeeping
    }
}

extern "C" void kernel_launch(void* const* d_in, const int* in_sizes, int n_in,
                              void* d_out, int out_size) {
    const float* inputs = (const float*)d_in[0];   // [256, 4096, 8]
    const float* W_in   = (const float*)d_in[1];   // [8, 64]
    const float* bias   = (const float*)d_in[2];   // [64]
    const float* W_rec  = (const float*)d_in[3];   // [64, 64]
    float* out = (float*)d_out;                    // [256, 4096, 64]

    esn_prep_kernel<<<1, UNITS>>>(W_rec);
    esn_main_kernel<<<BATCH, 32>>>(inputs, W_in, bias, out);
}

// round 2
// speedup vs baseline: 1.0065x; 1.0065x over previous
#include <cuda_runtime.h>
#include <cuda_bf16.h>
#include <cstdint>

// ESN reservoir: B=256, T=4096, D=8, U=64, leaky=1.0
// state_t = tanh(inputs[b,t,:] @ W_in + b + state_{t-1} @ W_rec)
// W_rec ~1.6% dense (~64 nnz). State lives in registers (2 units/lane);
// recurrent gather done with single-register __shfl_sync per nonzero by
// splitting each column's nonzero list by source half (reg n0 vs n1).

#define BATCH 256
#define TLEN  4096
#define DIN   8
#define UNITS 64
#define CAPL  6            // nonzeros with source unit < 32  (read via n0)
#define CAPH  6            // nonzeros with source unit >= 32 (read via n1)
#define CHUNK 64           // timesteps of input staged per cp.async group
#define NCHUNK (TLEN / CHUNK)
#define FULLMASK 0xffffffffu

// Per-column (destination unit) split nonzero lists, zero-padded.
__device__ int   g_srcL[UNITS][CAPL];   // source lane (0..31), unit = lane
__device__ float g_valL[UNITS][CAPL];
__device__ int   g_srcH[UNITS][CAPH];   // source lane (0..31), unit = lane+32
__device__ float g_valH[UNITS][CAPH];

__global__ void esn_prep_kernel(const float* __restrict__ W_rec) {
    int u = threadIdx.x;
    if (u >= UNITS) return;
    int cl = 0, ch = 0;
    for (int j = 0; j < UNITS; ++j) {
        float v = W_rec[j * UNITS + u];
        if (v != 0.0f) {
            if (j < 32) {
                if (cl < CAPL) { g_srcL[u][cl] = j;      g_valL[u][cl] = v; ++cl; }
            } else {
                if (ch < CAPH) { g_srcH[u][ch] = j - 32; g_valH[u][ch] = v; ++ch; }
            }
        }
    }
    for (int k = cl; k < CAPL; ++k) { g_srcL[u][k] = 0; g_valL[u][k] = 0.0f; }
    for (int k = ch; k < CAPH; ++k) { g_srcH[u][k] = 0; g_valH[u][k] = 0.0f; }
}

// tanh(x) = (e - 1) / (e + 1), e = exp(2x) via ex2.approx + rcp.approx.
// Chain: mul(4)+ex2(16)+add(4)+rcp(16)+mul(4) = 44 cyc. Rel err ~1e-6
// except |x|<1e-3 where cancellation gives ~1e-4 rel (1e-8 absolute).
__device__ __forceinline__ float fast_tanh(float x) {
    float e;
    asm("ex2.approx.f32 %0, %1;" : "=f"(e) : "f"(x * 2.8853900817779268f));
    float r;
    asm("rcp.approx.f32 %0, %1;" : "=f"(r) : "f"(e + 1.0f));
    return (e - 1.0f) * r;
}

__device__ __forceinline__ void cp_async16(void* smem_dst, const void* gmem_src) {
    uint32_t s = (uint32_t)__cvta_generic_to_shared(smem_dst);
    asm volatile("cp.async.cg.shared.global [%0], [%1], 16;\n" :: "r"(s), "l"(gmem_src));
}
__device__ __forceinline__ void cp_async_commit() {
    asm volatile("cp.async.commit_group;\n");
}
__device__ __forceinline__ void cp_async_wait1() {
    asm volatile("cp.async.wait_group 1;\n");
}

__global__ void __launch_bounds__(32, 8)
esn_main_kernel(const float* __restrict__ inputs,
                const float* __restrict__ W_in,
                const float* __restrict__ bias,
                float* __restrict__ out) {
    const int b    = blockIdx.x;
    const int lane = threadIdx.x;          // owns units lane and lane+32

    __shared__ float xin[2][CHUNK * DIN];  // double-buffered staged inputs

    // Input projection weights (registers)
    float win0[DIN], win1[DIN];
#pragma unroll
    for (int d = 0; d < DIN; ++d) {
        win0[d] = W_in[d * UNITS + lane];
        win1[d] = W_in[d * UNITS + lane + 32];
    }
    const float b0 = bias[lane];
    const float b1 = bias[lane + 32];

    // Sparse lists for both destination units (registers)
    int   sL0[CAPL], sH0[CAPH], sL1[CAPL], sH1[CAPH];
    float vL0[CAPL], vH0[CAPH], vL1[CAPL], vH1[CAPH];
#pragma unroll
    for (int k = 0; k < CAPL; ++k) {
        sL0[k] = g_srcL[lane][k];       vL0[k] = g_valL[lane][k];
        sL1[k] = g_srcL[lane + 32][k];  vL1[k] = g_valL[lane + 32][k];
    }
#pragma unroll
    for (int k = 0; k < CAPH; ++k) {
        sH0[k] = g_srcH[lane][k];       vH0[k] = g_valH[lane][k];
        sH1[k] = g_srcH[lane + 32][k];  vH1[k] = g_valH[lane + 32][k];
    }

    float n0 = 0.0f;   // state of unit `lane`
    float n1 = 0.0f;   // state of unit `lane+32`

    const float* inp_b = inputs + (size_t)b * TLEN * DIN;
    float*       out_b = out    + (size_t)b * TLEN * UNITS;

    // Prefetch input chunks 0 and 1 (2048B each; lane copies 4x16B).
#pragma unroll
    for (int c = 0; c < 2; ++c) {
        const float* src = inp_b + c * CHUNK * DIN;
#pragma unroll
        for (int i = 0; i < 4; ++i) {
            int fo = lane * 16 + i * 4;
            cp_async16(&xin[c][fo], src + fo);
        }
        cp_async_commit();
    }

    for (int c = 0; c < NCHUNK; ++c) {
        cp_async_wait1();
        __syncwarp();
        const int buf = c & 1;

#pragma unroll 4
        for (int tt = 0; tt < CHUNK; ++tt) {
            const int t = c * CHUNK + tt;

            // input vector (broadcast LDS.128 x2, off-chain)
            const float4 xa = *(const float4*)&xin[buf][tt * DIN];
            const float4 xb = *(const float4*)&xin[buf][tt * DIN + 4];

            // input projection: 2-accumulator trees, independent of state
            float q0 = fmaf(win0[0], xa.x, b0);
            float q1 = win0[1] * xa.y;
            q0 = fmaf(win0[2], xa.z, q0);
            q1 = fmaf(win0[3], xa.w, q1);
            q0 = fmaf(win0[4], xb.x, q0);
            q1 = fmaf(win0[5], xb.y, q1);
            q0 = fmaf(win0[6], xb.z, q0);
            q1 = fmaf(win0[7], xb.w, q1);
            const float xp0 = q0 + q1;

            float r0 = fmaf(win1[0], xa.x, b1);
            float r1 = win1[1] * xa.y;
            r0 = fmaf(win1[2], xa.z, r0);
            r1 = fmaf(win1[3], xa.w, r1);
            r0 = fmaf(win1[4], xb.x, r0);
            r1 = fmaf(win1[5], xb.y, r1);
            r0 = fmaf(win1[6], xb.z, r0);
            r1 = fmaf(win1[7], xb.w, r1);
            const float xp1 = r0 + r1;

            // recurrent gather via single-register shuffles, 4-way trees
            float a[4] = {xp0, 0.0f, 0.0f, 0.0f};
#pragma unroll
            for (int k = 0; k < CAPL; ++k)
                a[k & 3] = fmaf(vL0[k], __shfl_sync(FULLMASK, n0, sL0[k]), a[k & 3]);
#pragma unroll
            for (int k = 0; k < CAPH; ++k)
                a[(k + 2) & 3] = fmaf(vH0[k], __shfl_sync(FULLMASK, n1, sH0[k]), a[(k + 2) & 3]);
            const float z0 = (a[0] + a[1]) + (a[2] + a[3]);

            float d[4] = {xp1, 0.0f, 0.0f, 0.0f};
#pragma unroll
            for (int k = 0; k < CAPL; ++k)
                d[k & 3] = fmaf(vL1[k], __shfl_sync(FULLMASK, n0, sL1[k]), d[k & 3]);
#pragma unroll
            for (int k = 0; k < CAPH; ++k)
                d[(k + 2) & 3] = fmaf(vH1[k], __shfl_sync(FULLMASK, n1, sH1[k]), d[(k + 2) & 3]);
            const float z1 = (d[0] + d[1]) + (d[2] + d[3]);

            n0 = fast_tanh(z0);
            n1 = fast_tanh(z1);

            // output store (fire-and-forget, coalesced)
            out_b[(size_t)t * UNITS + lane]      = n0;
            out_b[(size_t)t * UNITS + lane + 32] = n1;
        }

        // prefetch chunk c+2 into the buffer just consumed
        if (c + 2 < NCHUNK) {
            const float* src = inp_b + (c + 2) * CHUNK * DIN;
#pragma unroll
            for (int i = 0; i < 4; ++i) {
                int fo = lane * 16 + i * 4;
                cp_async16(&xin[buf][fo], src + fo);
            }
        }
        cp_async_commit();  // keep wait_group bookkeeping consistent
    }
}

extern "C" void kernel_launch(void* const* d_in, const int* in_sizes, int n_in,
                              void* d_out, int out_size) {
    const float* inputs = (const float*)d_in[0];   // [256, 4096, 8]
    const float* W_in   = (const float*)d_in[1];   // [8, 64]
    const float* bias   = (const float*)d_in[2];   // [64]
    const float* W_rec  = (const float*)d_in[3];   // [64, 64]
    float* out = (float*)d_out;                    // [256, 4096, 64]

    esn_prep_kernel<<<1, UNITS>>>(W_rec);
    esn_main_kernel<<<BATCH, 32>>>(inputs, W_in, bias, out);
}